// round 15
// baseline (speedup 1.0000x reference)
#include <cuda_runtime.h>
#include <cuda_fp16.h>
#include <cstdint>

#define FULLMASK 0xFFFFFFFFu

namespace {
constexpr int   B       = 16;
constexpr int   NQ      = 8;
constexpr int   NS      = 16384;
constexpr int   D       = 128;
constexpr int   H       = 512;
constexpr int   ITERS   = 3;
constexpr float LN_EPS  = 1e-5f;
constexpr float EPS_A   = 1e-8f;
constexpr float SCALE   = 0.088388347648318447f;   // 128^-0.5
constexpr int   AW      = 4;                       // warps per attn block
constexpr int   TPW     = 4;                       // 16-row tiles per warp
constexpr int   ROWS_PB = AW * TPW * 16;           // 256 rows per attn block
constexpr int   ABLK    = NS / ROWS_PB;            // 64 attn blocks per batch
constexpr int   D2      = D / 2;                   // half2 elements per row
}

// ---- scratch (static __device__ arrays: allocation-free) ----
__device__ __half2 g_xn[(size_t)B * NS * D2];     // LayerNorm'd inputs, fp16, 67 MB
__device__ float g_slots[B * NQ * D];
__device__ float g_qk[B * NQ * D];                // SCALE * (q @ Wk)
__device__ float g_tt[B * NQ];                    // SCALE * (q . bk)
__device__ float g_Upart[(size_t)B * ABLK * NQ * D]; // per-block U partials, 4 MB
__device__ float g_denpart[B * ABLK * NQ];           // per-block den partials

// ============================================================
// Kernel 1: xn = fp16(LayerNorm(inputs)) — one warp per row
// ============================================================
__global__ void ln_in_kernel(const float* __restrict__ inp,
                             const float* __restrict__ w,
                             const float* __restrict__ b) {
    int warp = threadIdx.x >> 5, lane = threadIdx.x & 31;
    size_t row = (size_t)blockIdx.x * 8 + warp;
    const float4 x = *(const float4*)(inp + row * D + lane * 4);
    float s = x.x + x.y + x.z + x.w;
#pragma unroll
    for (int m = 16; m; m >>= 1) s += __shfl_xor_sync(FULLMASK, s, m);
    float mean = s * (1.0f / D);
    float dx = x.x - mean, dy = x.y - mean, dz = x.z - mean, dw = x.w - mean;
    float ss = dx * dx + dy * dy + dz * dz + dw * dw;
#pragma unroll
    for (int m = 16; m; m >>= 1) ss += __shfl_xor_sync(FULLMASK, ss, m);
    float rstd = rsqrtf(ss * (1.0f / D) + LN_EPS);
    const float4 wv = *(const float4*)(w + lane * 4);
    const float4 bv = *(const float4*)(b + lane * 4);
    float ox = dx * rstd * wv.x + bv.x;
    float oy = dy * rstd * wv.y + bv.y;
    float oz = dz * rstd * wv.z + bv.z;
    float ow = dw * rstd * wv.w + bv.w;
    __half2 h0 = __floats2half2_rn(ox, oy);
    __half2 h1 = __floats2half2_rn(oz, ow);
    uint2 packed;
    packed.x = *reinterpret_cast<uint32_t*>(&h0);
    packed.y = *reinterpret_cast<uint32_t*>(&h1);
    *(uint2*)(g_xn + row * D2 + lane * 2) = packed;
}

__global__ void init_slots_kernel(const float* __restrict__ q) {
    int i = blockIdx.x * blockDim.x + threadIdx.x;
    g_slots[i] = q[i];
}

// 512-thread block sum (16 warps); returns full-block sum to all threads
__device__ __forceinline__ float blockSum512(float v, float* red) {
#pragma unroll
    for (int m = 16; m; m >>= 1) v += __shfl_xor_sync(FULLMASK, v, m);
    __syncthreads();
    if ((threadIdx.x & 31) == 0) red[threadIdx.x >> 5] = v;
    __syncthreads();
    float s = 0.f;
#pragma unroll
    for (int i = 0; i < 16; i++) s += red[i];
    return s;
}

// quad reduce: sum across lanes 4k..4k+3 (thread = e*4+q)
__device__ __forceinline__ float quadSum(float v) {
    v += __shfl_xor_sync(FULLMASK, v, 1);
    v += __shfl_xor_sync(FULLMASK, v, 2);
    return v;
}

// 32-element quarter-dot with float4 loads, 4 independent chains
__device__ __forceinline__ float qdot(const float* __restrict__ vec,
                                      const float* __restrict__ mat_row, int q) {
    float a0 = 0.f, a1 = 0.f, a2 = 0.f, a3 = 0.f;
    const float4* m = (const float4*)(mat_row + q * 32);
    const float4* s = (const float4*)(vec + q * 32);
#pragma unroll
    for (int j = 0; j < 8; j++) {
        float4 mv = m[j];
        float4 sv = s[j];
        a0 = fmaf(sv.x, mv.x, a0);
        a1 = fmaf(sv.y, mv.y, a1);
        a2 = fmaf(sv.z, mv.z, a2);
        a3 = fmaf(sv.w, mv.w, a3);
    }
    return (a0 + a1) + (a2 + a3);
}

// ============================================================
// Kernel 2 (iteration 0 only): q = LN(slots)@Wq^T+bq ;
// qk = SCALE*(q@Wk) ; tt = SCALE*(q.bk)
// ============================================================
__global__ void __launch_bounds__(512) pre_kernel(
        const float* __restrict__ wq, const float* __restrict__ bq,
        const float* __restrict__ wk, const float* __restrict__ bk,
        const float* __restrict__ lnw, const float* __restrict__ lnb) {
    int row = blockIdx.x;            // b*NQ + i
    int tid = threadIdx.x;
    int e = tid >> 2, q = tid & 3;
    __shared__ float sh[D], sq[D], red[16];
    float s = g_slots[row * D + e];                 // x4 redundant
    float mean = blockSum512(s, red) * (1.0f / (4 * D));
    float d0 = s - mean;
    float var = blockSum512(d0 * d0, red) * (1.0f / (4 * D));
    float rstd = rsqrtf(var + LN_EPS);
    if (q == 0) sh[e] = d0 * rstd * lnw[e] + lnb[e];
    __syncthreads();
    float acc = quadSum(qdot(sh, wq + e * D, q));
    if (q == 0) sq[e] = acc + bq[e];
    __syncthreads();
    float qk = 0.f;
#pragma unroll 8
    for (int j = 0; j < 32; j++) {
        int d = q * 32 + j;
        qk = fmaf(sq[d], wk[d * D + e], qk);
    }
    qk = quadSum(qk);
    if (q == 0) g_qk[row * D + e] = qk * SCALE;
    float tv = (q == 0) ? sq[e] * bk[e] : 0.f;
    float tb = blockSum512(tv, red);
    if (tid == 0) g_tt[row] = tb * SCALE;
}

// ============================================================
// PTX helpers for tensor-core attn
// ============================================================
__device__ __forceinline__ void ldsm_x4(uint32_t& r0, uint32_t& r1,
                                        uint32_t& r2, uint32_t& r3, uint32_t addr) {
    asm volatile("ldmatrix.sync.aligned.m8n8.x4.shared.b16 {%0,%1,%2,%3}, [%4];"
                 : "=r"(r0), "=r"(r1), "=r"(r2), "=r"(r3) : "r"(addr));
}
__device__ __forceinline__ void ldsm_x4_t(uint32_t& r0, uint32_t& r1,
                                          uint32_t& r2, uint32_t& r3, uint32_t addr) {
    asm volatile("ldmatrix.sync.aligned.m8n8.x4.trans.shared.b16 {%0,%1,%2,%3}, [%4];"
                 : "=r"(r0), "=r"(r1), "=r"(r2), "=r"(r3) : "r"(addr));
}
__device__ __forceinline__ void mma16816(float* c, uint32_t a0, uint32_t a1,
                                         uint32_t a2, uint32_t a3,
                                         uint32_t b0, uint32_t b1) {
    asm volatile("mma.sync.aligned.m16n8k16.row.col.f32.f16.f16.f32 "
                 "{%0,%1,%2,%3}, {%4,%5,%6,%7}, {%8,%9}, {%0,%1,%2,%3};"
                 : "+f"(c[0]), "+f"(c[1]), "+f"(c[2]), "+f"(c[3])
                 : "r"(a0), "r"(a1), "r"(a2), "r"(a3), "r"(b0), "r"(b1));
}
__device__ __forceinline__ uint32_t prmt_b32(uint32_t a, uint32_t b, uint32_t s) {
    uint32_t d;
    asm("prmt.b32 %0, %1, %2, %3;" : "=r"(d) : "r"(a), "r"(b), "r"(s));
    return d;
}
__device__ __forceinline__ void cp16(uint32_t smem_dst, const void* gsrc) {
    asm volatile("cp.async.cg.shared.global [%0], [%1], 16;"
                 :: "r"(smem_dst), "l"(gsrc));
}

// ============================================================
// Kernel 3 (per iter): tensor-core attention, cp.async
// double-buffered. Block: 128 thr (4 warps), warp = 64 rows.
// NO GLOBAL ATOMICS: each block stores its reduced partial to a
// private g_Upart/g_denpart slot (R14 post-mortem: the per-L2-line
// atomic serialization on g_U — 2048 ops/line x 30cy = 35us — was
// the real attn floor, not bandwidth).
//
// Frag mappings (verified, passing at 4e-6 since R7):
//   C: c0=(g,2t) c1=(g,2t+1) c2=(g+8,2t) c3=(g+8,2t+1)
//   B (k16xn8 col): b0=B[2t,2t+1][g], b1=B[2t+8,2t+9][g]
//   smem tile: 16 rows x 16 chunks(16B), chunk swizzle c^(r&7)
// ============================================================
__global__ void __launch_bounds__(128) attn_kernel() {
    int b = blockIdx.y, cx = blockIdx.x;
    int tid = threadIdx.x, w = tid >> 5, l = tid & 31;
    int g = l >> 2, t = l & 3;
    __shared__ uint4 sx[AW][2][256];      // 4 warps x 2 stages x 4KB = 32KB
    __shared__ __half sqk_h[NQ * D];      // fp16 qk, 2KB
    __shared__ float s_tt[NQ];
    __shared__ float sUsh[NQ * D];        // block-level U accumulator, 4KB
    __shared__ float sden[NQ];

    for (int i = tid; i < NQ * D; i += 128) {
        sqk_h[i] = __float2half(g_qk[b * NQ * D + i]);
        sUsh[i] = 0.f;
    }
    if (tid < NQ) { s_tt[tid] = g_tt[b * NQ + tid]; sden[tid] = 0.f; }
    __syncthreads();

    // qk B-frags (loop-invariant plain loads)
    uint32_t bq0[8], bq1[8];
#pragma unroll
    for (int ks = 0; ks < 8; ks++) {
        bq0[ks] = *(const uint32_t*)&sqk_h[g * D + ks * 16 + 2 * t];
        bq1[ks] = *(const uint32_t*)&sqk_h[g * D + ks * 16 + 8 + 2 * t];
    }
    float tb0 = s_tt[2 * t], tb1 = s_tt[2 * t + 1];

    uint32_t sb0 = (uint32_t)__cvta_generic_to_shared(&sx[w][0][0]);
    uint32_t sb1 = (uint32_t)__cvta_generic_to_shared(&sx[w][1][0]);
    int sub = l >> 3, rwl = l & 7;

    float U[8][4];
#pragma unroll
    for (int md = 0; md < 8; md++) { U[md][0] = 0.f; U[md][1] = 0.f; U[md][2] = 0.f; U[md][3] = 0.f; }
    float dc0 = 0.f, dc1 = 0.f;

    // warp's 64 rows start here (16 uint4 per row)
    const uint4* gx0 = (const uint4*)g_xn +
        ((size_t)b * NS + (size_t)cx * ROWS_PB + w * (16 * TPW)) * 16;

    // prologue: stream tile 0 into stage 0
#pragma unroll
    for (int i = 0; i < 8; i++) {
        int idx = i * 32 + l, row = idx >> 4, c = idx & 15;
        cp16(sb0 + (uint32_t)(row * 16 + (c ^ (row & 7))) * 16u, gx0 + idx);
    }
    asm volatile("cp.async.commit_group;");

    for (int tile = 0; tile < TPW; tile++) {
        if (tile + 1 < TPW) {
            const uint4* gx = gx0 + (size_t)(tile + 1) * 256;
            uint32_t dstb = ((tile + 1) & 1) ? sb1 : sb0;
#pragma unroll
            for (int i = 0; i < 8; i++) {
                int idx = i * 32 + l, row = idx >> 4, c = idx & 15;
                cp16(dstb + (uint32_t)(row * 16 + (c ^ (row & 7))) * 16u, gx + idx);
            }
            asm volatile("cp.async.commit_group;");
            asm volatile("cp.async.wait_group 1;");
        } else {
            asm volatile("cp.async.wait_group 0;");
        }
        __syncwarp();
        uint32_t sb = (tile & 1) ? sb1 : sb0;

        // ---- Phase A: P = X @ qk^T ----
        float p[4] = {0.f, 0.f, 0.f, 0.f};
#pragma unroll
        for (int ks = 0; ks < 8; ks++) {
            int ar = (sub & 1) * 8 + rwl;
            int ac = 2 * ks + (sub >> 1);
            uint32_t addr = sb + (uint32_t)(ar * 16 + (ac ^ (ar & 7))) * 16u;
            uint32_t a0, a1, a2, a3;
            ldsm_x4(a0, a1, a2, a3, addr);
            mma16816(p, a0, a1, a2, a3, bq0[ks], bq1[ks]);
        }

        // ---- softmax over queries (cols) ----
        float e00 = __expf(p[0] + tb0), e01 = __expf(p[1] + tb1);
        float e10 = __expf(p[2] + tb0), e11 = __expf(p[3] + tb1);
        float s0 = e00 + e01, s1 = e10 + e11;
        s0 += __shfl_xor_sync(FULLMASK, s0, 1);
        s0 += __shfl_xor_sync(FULLMASK, s0, 2);
        s1 += __shfl_xor_sync(FULLMASK, s1, 1);
        s1 += __shfl_xor_sync(FULLMASK, s1, 2);
        float i0 = __fdividef(1.f, s0), i1 = __fdividef(1.f, s1);
        float a00 = fmaf(e00, i0, EPS_A), a01 = fmaf(e01, i0, EPS_A);
        float a10 = fmaf(e10, i1, EPS_A), a11 = fmaf(e11, i1, EPS_A);
        dc0 += a00 + a10;
        dc1 += a01 + a11;

        // ---- transpose a into U-GEMM B-frag via shfl+prmt ----
        __half2 hp0 = __floats2half2_rn(a00, a01);
        __half2 hp1 = __floats2half2_rn(a10, a11);
        uint32_t p0 = *reinterpret_cast<uint32_t*>(&hp0);
        uint32_t p1 = *reinterpret_cast<uint32_t*>(&hp1);
        int l0 = (2 * t) * 4 + (g >> 1);
        int l1 = (2 * t + 1) * 4 + (g >> 1);
        uint32_t s00 = __shfl_sync(FULLMASK, p0, l0);
        uint32_t s01 = __shfl_sync(FULLMASK, p0, l1);
        uint32_t s10 = __shfl_sync(FULLMASK, p1, l0);
        uint32_t s11 = __shfl_sync(FULLMASK, p1, l1);
        uint32_t sel = (g & 1) ? 0x7632u : 0x5410u;
        uint32_t bU0 = prmt_b32(s00, s01, sel);
        uint32_t bU1 = prmt_b32(s10, s11, sel);

        // ---- Phase B: U^T += X^T @ A (accumulates across tiles) ----
#pragma unroll
        for (int md = 0; md < 8; md++) {
            int ar = (sub >> 1) * 8 + rwl;
            int ac = 2 * md + (sub & 1);
            uint32_t addr = sb + (uint32_t)(ar * 16 + (ac ^ (ar & 7))) * 16u;
            uint32_t a0, a1, a2, a3;
            ldsm_x4_t(a0, a1, a2, a3, addr);
            mma16816(U[md], a0, a1, a2, a3, bU0, bU1);
        }
        __syncwarp();      // all reads done before this stage is overwritten
    }

    // ---- block-level reduction in shared (distinct addrs per lane) ----
#pragma unroll
    for (int md = 0; md < 8; md++) {
        int d0 = md * 16 + g;
        atomicAdd(&sUsh[(2 * t) * D + d0],         U[md][0]);
        atomicAdd(&sUsh[(2 * t + 1) * D + d0],     U[md][1]);
        atomicAdd(&sUsh[(2 * t) * D + d0 + 8],     U[md][2]);
        atomicAdd(&sUsh[(2 * t + 1) * D + d0 + 8], U[md][3]);
    }
    dc0 += __shfl_xor_sync(FULLMASK, dc0, 4);
    dc0 += __shfl_xor_sync(FULLMASK, dc0, 8);
    dc0 += __shfl_xor_sync(FULLMASK, dc0, 16);
    dc1 += __shfl_xor_sync(FULLMASK, dc1, 4);
    dc1 += __shfl_xor_sync(FULLMASK, dc1, 8);
    dc1 += __shfl_xor_sync(FULLMASK, dc1, 16);
    if (l < 4) {                       // lanes t=0..3 cover query cols 0..7
        atomicAdd(&sden[2 * t], dc0);
        atomicAdd(&sden[2 * t + 1], dc1);
    }
    __syncthreads();

    // ---- plain coalesced store to this block's private partial slot ----
    size_t part = (size_t)(b * ABLK + cx);
    float* gU = g_Upart + part * (NQ * D);
    for (int i = tid; i < NQ * D; i += 128) gU[i] = sUsh[i];
    if (tid < NQ) g_denpart[part * NQ + tid] = sden[tid];
}

// ============================================================
// Kernel 4 (per iter): reduce partials ; updates = (U/den)@Wv^T+bv ;
// GRU ; slots+FF.  do_pre != 0: fused next-iteration qk/tt.
// ============================================================
__global__ void __launch_bounds__(512) post_kernel(
        const float* __restrict__ wv, const float* __restrict__ bv,
        const float* __restrict__ gwi, const float* __restrict__ gwh,
        const float* __restrict__ gbi, const float* __restrict__ gbh,
        const float* __restrict__ w1, const float* __restrict__ b1,
        const float* __restrict__ w2, const float* __restrict__ b2,
        const float* __restrict__ lnw, const float* __restrict__ lnb,
        const float* __restrict__ wq, const float* __restrict__ bq,
        const float* __restrict__ wk, const float* __restrict__ bk,
        const float* __restrict__ lnqw, const float* __restrict__ lnqb,
        float* __restrict__ out, int write_out, int do_pre) {
    int row = blockIdx.x;
    int tid = threadIdx.x;
    int e = tid >> 2, q = tid & 3;
    int bb = row >> 3, ii = row & 7;                // batch, query
    __shared__ float sU[D], sUpd[D], sS[D], sM[H], red[16], sdp[ABLK];
    // ---- reduce den partials ----
    if (tid < ABLK) sdp[tid] = g_denpart[(bb * ABLK + tid) * NQ + ii];
    __syncthreads();
    float den = 0.f;
#pragma unroll 8
    for (int j = 0; j < ABLK; j++) den += sdp[j];   // broadcast reads
    // ---- reduce U partials: thread (e,q) sums 16 of 64 chunks ----
    float up = 0.f;
#pragma unroll 4
    for (int j = 0; j < ABLK / 4; j++)
        up += g_Upart[((size_t)(bb * ABLK + q * (ABLK / 4) + j) * NQ + ii) * D + e];
    up = quadSum(up);
    float slot = g_slots[row * D + e];              // x4 redundant
    if (q == 0) {
        sU[e] = up / den;
        sS[e] = slot;
    }
    __syncthreads();
    float upd = quadSum(qdot(sU, wv + e * D, q));
    if (q == 0) sUpd[e] = upd + bv[e];
    __syncthreads();
    float gi[3], gh[3];
#pragma unroll
    for (int k = 0; k < 3; k++) {
        int gg = e + k * D;
        float ai = quadSum(qdot(sUpd, gwi + gg * D, q));
        float ah = quadSum(qdot(sS, gwh + gg * D, q));
        gi[k] = ai + gbi[gg];
        gh[k] = ah + gbh[gg];
    }
    float r = 1.0f / (1.0f + __expf(-(gi[0] + gh[0])));
    float z = 1.0f / (1.0f + __expf(-(gi[1] + gh[1])));
    float n = tanhf(gi[2] + r * gh[2]);
    float snew = (1.0f - z) * n + z * slot;         // same in all 4 roles
    float mean = blockSum512(snew, red) * (1.0f / (4 * D));
    float d0 = snew - mean;
    float var = blockSum512(d0 * d0, red) * (1.0f / (4 * D));
    float rstd = rsqrtf(var + LN_EPS);
    if (q == 0) sU[e] = d0 * rstd * lnw[e] + lnb[e];   // reuse sU as hidden
    __syncthreads();
    {
        float a0 = 0.f, a1 = 0.f, a2 = 0.f, a3 = 0.f;
        const float4* m = (const float4*)(w1 + tid * D);
        const float4* s4 = (const float4*)(sU);
#pragma unroll
        for (int j = 0; j < 32; j++) {
            float4 mv = m[j];
            float4 sv = s4[j];
            a0 = fmaf(sv.x, mv.x, a0);
            a1 = fmaf(sv.y, mv.y, a1);
            a2 = fmaf(sv.z, mv.z, a2);
            a3 = fmaf(sv.w, mv.w, a3);
        }
        sM[tid] = fmaxf((a0 + a1) + (a2 + a3) + b1[tid], 0.f);
    }
    __syncthreads();
    float onew;
    {
        float a0 = 0.f, a1 = 0.f, a2 = 0.f, a3 = 0.f;
        const float4* m = (const float4*)(w2 + e * H + q * 128);
        const float4* s4 = (const float4*)(sM + q * 128);
#pragma unroll
        for (int j = 0; j < 32; j++) {
            float4 mv = m[j];
            float4 sv = s4[j];
            a0 = fmaf(sv.x, mv.x, a0);
            a1 = fmaf(sv.y, mv.y, a1);
            a2 = fmaf(sv.z, mv.z, a2);
            a3 = fmaf(sv.w, mv.w, a3);
        }
        onew = quadSum((a0 + a1) + (a2 + a3)) + b2[e] + snew;  // all lanes
        if (q == 0) {
            g_slots[row * D + e] = onew;
            if (write_out) out[row * D + e] = onew;
        }
    }
    if (!do_pre) return;

    // ---- fused pre for the NEXT iteration (onew in registers) ----
    __syncthreads();
    float mean2 = blockSum512(onew, red) * (1.0f / (4 * D));
    float dd = onew - mean2;
    float var2 = blockSum512(dd * dd, red) * (1.0f / (4 * D));
    float rstd2 = rsqrtf(var2 + LN_EPS);
    if (q == 0) sS[e] = dd * rstd2 * lnqw[e] + lnqb[e];   // reuse sS as h
    __syncthreads();
    float accq = quadSum(qdot(sS, wq + e * D, q));
    if (q == 0) sUpd[e] = accq + bq[e];                   // reuse sUpd as qvec
    __syncthreads();
    float qk = 0.f;
#pragma unroll 8
    for (int j = 0; j < 32; j++) {
        int d = q * 32 + j;
        qk = fmaf(sUpd[d], wk[d * D + e], qk);
    }
    qk = quadSum(qk);
    if (q == 0) g_qk[row * D + e] = qk * SCALE;
    float tv = (q == 0) ? sUpd[e] * bk[e] : 0.f;
    float tb = blockSum512(tv, red);
    if (tid == 0) g_tt[row] = tb * SCALE;
}

// ============================================================
extern "C" void kernel_launch(void* const* d_in, const int* in_sizes, int n_in,
                              void* d_out, int out_size) {
    (void)in_sizes; (void)n_in; (void)out_size;
    const float* queries = (const float*)d_in[0];
    const float* inputs  = (const float*)d_in[1];
    const float* wq  = (const float*)d_in[2];
    const float* bq  = (const float*)d_in[3];
    const float* wk  = (const float*)d_in[4];
    const float* bk  = (const float*)d_in[5];
    const float* wv  = (const float*)d_in[6];
    const float* bv  = (const float*)d_in[7];
    const float* gwi = (const float*)d_in[8];
    const float* gwh = (const float*)d_in[9];
    const float* gbi = (const float*)d_in[10];
    const float* gbh = (const float*)d_in[11];
    const float* w1  = (const float*)d_in[12];
    const float* b1  = (const float*)d_in[13];
    const float* w2  = (const float*)d_in[14];
    const float* b2  = (const float*)d_in[15];
    const float* ln_in_w = (const float*)d_in[16];
    const float* ln_in_b = (const float*)d_in[17];
    const float* ln_q_w  = (const float*)d_in[18];
    const float* ln_q_b  = (const float*)d_in[19];
    const float* ln_ff_w = (const float*)d_in[20];
    const float* ln_ff_b = (const float*)d_in[21];
    float* out = (float*)d_out;

    ln_in_kernel<<<B * NS / 8, 256>>>(inputs, ln_in_w, ln_in_b);
    init_slots_kernel<<<B * NQ * D / 256, 256>>>(queries);
    pre_kernel<<<B * NQ, 512>>>(wq, bq, wk, bk, ln_q_w, ln_q_b);
    for (int it = 0; it < ITERS; it++) {
        attn_kernel<<<dim3(ABLK, B), 128>>>();
        post_kernel<<<B * NQ, 512>>>(wv, bv, gwi, gwh, gbi, gbh,
                                     w1, b1, w2, b2, ln_ff_w, ln_ff_b,
                                     wq, bq, wk, bk, ln_q_w, ln_q_b,
                                     out, it == ITERS - 1 ? 1 : 0,
                                     it < ITERS - 1 ? 1 : 0);
    }
}

// round 16
// speedup vs baseline: 1.1368x; 1.1368x over previous
#include <cuda_runtime.h>
#include <cuda_fp16.h>
#include <cstdint>

#define FULLMASK 0xFFFFFFFFu

namespace {
constexpr int   B       = 16;
constexpr int   NQ      = 8;
constexpr int   NS      = 16384;
constexpr int   D       = 128;
constexpr int   H       = 512;
constexpr int   ITERS   = 3;
constexpr float LN_EPS  = 1e-5f;
constexpr float EPS_A   = 1e-8f;
constexpr float SCALE   = 0.088388347648318447f;   // 128^-0.5
constexpr int   AW      = 4;                       // warps per attn block
constexpr int   TPW     = 8;                       // 16-row tiles per warp
constexpr int   ROWS_PB = AW * TPW * 16;           // 512 rows per attn block
constexpr int   ABLK    = NS / ROWS_PB;            // 32 attn blocks per batch
constexpr int   D2      = D / 2;                   // half2 elements per row
}

// ---- scratch (static __device__ arrays: allocation-free) ----
__device__ __half2 g_xn[(size_t)B * NS * D2];     // LayerNorm'd inputs, fp16, 67 MB
__device__ float g_slots[B * NQ * D];
__device__ float g_qk[B * NQ * D];                // SCALE * (q @ Wk)
__device__ float g_tt[B * NQ];                    // SCALE * (q . bk)
__device__ float g_Upart[(size_t)B * ABLK * NQ * D]; // per-block U partials
__device__ float g_denpart[B * ABLK * NQ];           // per-block den partials

// ============================================================
// Kernel 1: xn = fp16(LayerNorm(inputs)) — one warp per row
// ============================================================
__global__ void ln_in_kernel(const float* __restrict__ inp,
                             const float* __restrict__ w,
                             const float* __restrict__ b) {
    int warp = threadIdx.x >> 5, lane = threadIdx.x & 31;
    size_t row = (size_t)blockIdx.x * 8 + warp;
    const float4 x = *(const float4*)(inp + row * D + lane * 4);
    float s = x.x + x.y + x.z + x.w;
#pragma unroll
    for (int m = 16; m; m >>= 1) s += __shfl_xor_sync(FULLMASK, s, m);
    float mean = s * (1.0f / D);
    float dx = x.x - mean, dy = x.y - mean, dz = x.z - mean, dw = x.w - mean;
    float ss = dx * dx + dy * dy + dz * dz + dw * dw;
#pragma unroll
    for (int m = 16; m; m >>= 1) ss += __shfl_xor_sync(FULLMASK, ss, m);
    float rstd = rsqrtf(ss * (1.0f / D) + LN_EPS);
    const float4 wv = *(const float4*)(w + lane * 4);
    const float4 bv = *(const float4*)(b + lane * 4);
    float ox = dx * rstd * wv.x + bv.x;
    float oy = dy * rstd * wv.y + bv.y;
    float oz = dz * rstd * wv.z + bv.z;
    float ow = dw * rstd * wv.w + bv.w;
    __half2 h0 = __floats2half2_rn(ox, oy);
    __half2 h1 = __floats2half2_rn(oz, ow);
    uint2 packed;
    packed.x = *reinterpret_cast<uint32_t*>(&h0);
    packed.y = *reinterpret_cast<uint32_t*>(&h1);
    *(uint2*)(g_xn + row * D2 + lane * 2) = packed;
}

// 512-thread block sum; returns full-block sum to all threads
__device__ __forceinline__ float blockSum512(float v, float* red) {
#pragma unroll
    for (int m = 16; m; m >>= 1) v += __shfl_xor_sync(FULLMASK, v, m);
    __syncthreads();
    if ((threadIdx.x & 31) == 0) red[threadIdx.x >> 5] = v;
    __syncthreads();
    float s = 0.f;
#pragma unroll
    for (int i = 0; i < 16; i++) s += red[i];
    return s;
}

// 1024-thread block sum
__device__ __forceinline__ float blockSum1024(float v, float* red) {
#pragma unroll
    for (int m = 16; m; m >>= 1) v += __shfl_xor_sync(FULLMASK, v, m);
    __syncthreads();
    if ((threadIdx.x & 31) == 0) red[threadIdx.x >> 5] = v;
    __syncthreads();
    float s = 0.f;
#pragma unroll
    for (int i = 0; i < 32; i++) s += red[i];
    return s;
}

__device__ __forceinline__ float quadSum(float v) {
    v += __shfl_xor_sync(FULLMASK, v, 1);
    v += __shfl_xor_sync(FULLMASK, v, 2);
    return v;
}
__device__ __forceinline__ float octSum(float v) {
    v += __shfl_xor_sync(FULLMASK, v, 1);
    v += __shfl_xor_sync(FULLMASK, v, 2);
    v += __shfl_xor_sync(FULLMASK, v, 4);
    return v;
}

// 32-element quarter-dot (q in 0..3), float4 loads
__device__ __forceinline__ float qdot(const float* __restrict__ vec,
                                      const float* __restrict__ mat_row, int q) {
    float a0 = 0.f, a1 = 0.f, a2 = 0.f, a3 = 0.f;
    const float4* m = (const float4*)(mat_row + q * 32);
    const float4* s = (const float4*)(vec + q * 32);
#pragma unroll
    for (int j = 0; j < 8; j++) {
        float4 mv = m[j];
        float4 sv = s[j];
        a0 = fmaf(sv.x, mv.x, a0);
        a1 = fmaf(sv.y, mv.y, a1);
        a2 = fmaf(sv.z, mv.z, a2);
        a3 = fmaf(sv.w, mv.w, a3);
    }
    return (a0 + a1) + (a2 + a3);
}

// 16-element eighth-dot (q in 0..7), float4 loads
__device__ __forceinline__ float qdot16(const float* __restrict__ vec,
                                        const float* __restrict__ mat_row, int q) {
    float a0 = 0.f, a1 = 0.f, a2 = 0.f, a3 = 0.f;
    const float4* m = (const float4*)(mat_row + q * 16);
    const float4* s = (const float4*)(vec + q * 16);
#pragma unroll
    for (int j = 0; j < 4; j++) {
        float4 mv = m[j];
        float4 sv = s[j];
        a0 = fmaf(sv.x, mv.x, a0);
        a1 = fmaf(sv.y, mv.y, a1);
        a2 = fmaf(sv.z, mv.z, a2);
        a3 = fmaf(sv.w, mv.w, a3);
    }
    return (a0 + a1) + (a2 + a3);
}

// ============================================================
// Kernel 2 (iteration 0 only): slots = queries (fold of init);
// q = LN(slots)@Wq^T+bq ; qk = SCALE*(q@Wk) ; tt = SCALE*(q.bk)
// ============================================================
__global__ void __launch_bounds__(512) pre_kernel(
        const float* __restrict__ queries,
        const float* __restrict__ wq, const float* __restrict__ bq,
        const float* __restrict__ wk, const float* __restrict__ bk,
        const float* __restrict__ lnw, const float* __restrict__ lnb) {
    int row = blockIdx.x;            // b*NQ + i
    int tid = threadIdx.x;
    int e = tid >> 2, q = tid & 3;
    __shared__ float sh[D], sq[D], red[16];
    float s = queries[row * D + e];                 // x4 redundant
    if (q == 0) g_slots[row * D + e] = s;           // init slots
    float mean = blockSum512(s, red) * (1.0f / (4 * D));
    float d0 = s - mean;
    float var = blockSum512(d0 * d0, red) * (1.0f / (4 * D));
    float rstd = rsqrtf(var + LN_EPS);
    if (q == 0) sh[e] = d0 * rstd * lnw[e] + lnb[e];
    __syncthreads();
    float acc = quadSum(qdot(sh, wq + e * D, q));
    if (q == 0) sq[e] = acc + bq[e];
    __syncthreads();
    float qk = 0.f;
#pragma unroll 8
    for (int j = 0; j < 32; j++) {
        int d = q * 32 + j;
        qk = fmaf(sq[d], wk[d * D + e], qk);
    }
    qk = quadSum(qk);
    if (q == 0) g_qk[row * D + e] = qk * SCALE;
    float tv = (q == 0) ? sq[e] * bk[e] : 0.f;
    float tb = blockSum512(tv, red);
    if (tid == 0) g_tt[row] = tb * SCALE;
}

// ============================================================
// PTX helpers
// ============================================================
__device__ __forceinline__ void ldsm_x4(uint32_t& r0, uint32_t& r1,
                                        uint32_t& r2, uint32_t& r3, uint32_t addr) {
    asm volatile("ldmatrix.sync.aligned.m8n8.x4.shared.b16 {%0,%1,%2,%3}, [%4];"
                 : "=r"(r0), "=r"(r1), "=r"(r2), "=r"(r3) : "r"(addr));
}
__device__ __forceinline__ void ldsm_x4_t(uint32_t& r0, uint32_t& r1,
                                          uint32_t& r2, uint32_t& r3, uint32_t addr) {
    asm volatile("ldmatrix.sync.aligned.m8n8.x4.trans.shared.b16 {%0,%1,%2,%3}, [%4];"
                 : "=r"(r0), "=r"(r1), "=r"(r2), "=r"(r3) : "r"(addr));
}
__device__ __forceinline__ void mma16816(float* c, uint32_t a0, uint32_t a1,
                                         uint32_t a2, uint32_t a3,
                                         uint32_t b0, uint32_t b1) {
    asm volatile("mma.sync.aligned.m16n8k16.row.col.f32.f16.f16.f32 "
                 "{%0,%1,%2,%3}, {%4,%5,%6,%7}, {%8,%9}, {%0,%1,%2,%3};"
                 : "+f"(c[0]), "+f"(c[1]), "+f"(c[2]), "+f"(c[3])
                 : "r"(a0), "r"(a1), "r"(a2), "r"(a3), "r"(b0), "r"(b1));
}
__device__ __forceinline__ uint32_t prmt_b32(uint32_t a, uint32_t b, uint32_t s) {
    uint32_t d;
    asm("prmt.b32 %0, %1, %2, %3;" : "=r"(d) : "r"(a), "r"(b), "r"(s));
    return d;
}
__device__ __forceinline__ void cp16(uint32_t smem_dst, const void* gsrc) {
    asm volatile("cp.async.cg.shared.global [%0], [%1], 16;"
                 :: "r"(smem_dst), "l"(gsrc));
}

// ============================================================
// Kernel 3 (per iter): tensor-core attention. R15 post-mortem:
// latency-bound (issue 19.6%, 16 warps/SM). Fixes: 5 blocks/SM
// via launch_bounds, phase-A split into 2 independent mma chains,
// qk B-frags from conflict-free smem table (16 fewer regs),
// TPW=8 -> single wave of 512 blocks.
//
// Frag mappings (verified since R7):
//   C: c0=(g,2t) c1=(g,2t+1) c2=(g+8,2t) c3=(g+8,2t+1)
//   B (k16xn8 col): b0=B[2t,2t+1][g], b1=B[2t+8,2t+9][g]
//   smem tile: 16 rows x 16 chunks(16B), chunk swizzle c^(r&7)
// ============================================================
__global__ void __launch_bounds__(128, 5) attn_kernel() {
    int b = blockIdx.y, cx = blockIdx.x;
    int tid = threadIdx.x, w = tid >> 5, l = tid & 31;
    int g = l >> 2, t = l & 3;
    __shared__ uint4 sx[AW][2][256];      // 4 warps x 2 stages x 4KB = 32KB
    __shared__ uint32_t sqkB[512];        // packed B-frags [ks][which][lane], 2KB
    __shared__ float s_tt[NQ];
    __shared__ float sUsh[NQ * D];        // block-level U accumulator, 4KB
    __shared__ float sden[NQ];

    // pre-pack qk B-frags, conflict-free lane-major layout
    for (int idx = tid; idx < 512; idx += 128) {
        int ks = idx >> 6, which = (idx >> 5) & 1, l2 = idx & 31;
        int g2 = l2 >> 2, t2 = l2 & 3;
        const float* qrow = g_qk + b * NQ * D + g2 * D + ks * 16 + which * 8 + 2 * t2;
        __half2 hp = __floats2half2_rn(qrow[0], qrow[1]);
        sqkB[idx] = *reinterpret_cast<uint32_t*>(&hp);
    }
    for (int i = tid; i < NQ * D; i += 128) sUsh[i] = 0.f;
    if (tid < NQ) { s_tt[tid] = g_tt[b * NQ + tid]; sden[tid] = 0.f; }
    __syncthreads();

    float tb0 = s_tt[2 * t], tb1 = s_tt[2 * t + 1];
    uint32_t sb0 = (uint32_t)__cvta_generic_to_shared(&sx[w][0][0]);
    uint32_t sb1 = (uint32_t)__cvta_generic_to_shared(&sx[w][1][0]);
    int sub = l >> 3, rwl = l & 7;

    float U[8][4];
#pragma unroll
    for (int md = 0; md < 8; md++) { U[md][0] = 0.f; U[md][1] = 0.f; U[md][2] = 0.f; U[md][3] = 0.f; }
    float dc0 = 0.f, dc1 = 0.f;

    const uint4* gx0 = (const uint4*)g_xn +
        ((size_t)b * NS + (size_t)cx * ROWS_PB + w * (16 * TPW)) * 16;

    // prologue: stream tile 0 into stage 0
#pragma unroll
    for (int i = 0; i < 8; i++) {
        int idx = i * 32 + l, row = idx >> 4, c = idx & 15;
        cp16(sb0 + (uint32_t)(row * 16 + (c ^ (row & 7))) * 16u, gx0 + idx);
    }
    asm volatile("cp.async.commit_group;");

    for (int tile = 0; tile < TPW; tile++) {
        if (tile + 1 < TPW) {
            const uint4* gx = gx0 + (size_t)(tile + 1) * 256;
            uint32_t dstb = ((tile + 1) & 1) ? sb1 : sb0;
#pragma unroll
            for (int i = 0; i < 8; i++) {
                int idx = i * 32 + l, row = idx >> 4, c = idx & 15;
                cp16(dstb + (uint32_t)(row * 16 + (c ^ (row & 7))) * 16u, gx + idx);
            }
            asm volatile("cp.async.commit_group;");
            asm volatile("cp.async.wait_group 1;");
        } else {
            asm volatile("cp.async.wait_group 0;");
        }
        __syncwarp();
        uint32_t sb = (tile & 1) ? sb1 : sb0;

        // ---- Phase A: P = X @ qk^T, two independent 4-step chains ----
        float pA[4] = {0.f, 0.f, 0.f, 0.f};
        float pB[4] = {0.f, 0.f, 0.f, 0.f};
#pragma unroll
        for (int ks = 0; ks < 8; ks++) {
            int ar = (sub & 1) * 8 + rwl;
            int ac = 2 * ks + (sub >> 1);
            uint32_t addr = sb + (uint32_t)(ar * 16 + (ac ^ (ar & 7))) * 16u;
            uint32_t a0, a1, a2, a3;
            ldsm_x4(a0, a1, a2, a3, addr);
            uint32_t b0 = sqkB[ks * 64 + l];
            uint32_t b1 = sqkB[ks * 64 + 32 + l];
            mma16816((ks & 1) ? pB : pA, a0, a1, a2, a3, b0, b1);
        }
        float p0s = pA[0] + pB[0], p1s = pA[1] + pB[1];
        float p2s = pA[2] + pB[2], p3s = pA[3] + pB[3];

        // ---- softmax over queries (cols) ----
        float e00 = __expf(p0s + tb0), e01 = __expf(p1s + tb1);
        float e10 = __expf(p2s + tb0), e11 = __expf(p3s + tb1);
        float s0 = e00 + e01, s1 = e10 + e11;
        s0 += __shfl_xor_sync(FULLMASK, s0, 1);
        s0 += __shfl_xor_sync(FULLMASK, s0, 2);
        s1 += __shfl_xor_sync(FULLMASK, s1, 1);
        s1 += __shfl_xor_sync(FULLMASK, s1, 2);
        float i0 = __fdividef(1.f, s0), i1 = __fdividef(1.f, s1);
        float a00 = fmaf(e00, i0, EPS_A), a01 = fmaf(e01, i0, EPS_A);
        float a10 = fmaf(e10, i1, EPS_A), a11 = fmaf(e11, i1, EPS_A);
        dc0 += a00 + a10;
        dc1 += a01 + a11;

        // ---- transpose a into U-GEMM B-frag via shfl+prmt ----
        __half2 hp0 = __floats2half2_rn(a00, a01);
        __half2 hp1 = __floats2half2_rn(a10, a11);
        uint32_t p0 = *reinterpret_cast<uint32_t*>(&hp0);
        uint32_t p1 = *reinterpret_cast<uint32_t*>(&hp1);
        int l0 = (2 * t) * 4 + (g >> 1);
        int l1 = (2 * t + 1) * 4 + (g >> 1);
        uint32_t s00 = __shfl_sync(FULLMASK, p0, l0);
        uint32_t s01 = __shfl_sync(FULLMASK, p0, l1);
        uint32_t s10 = __shfl_sync(FULLMASK, p1, l0);
        uint32_t s11 = __shfl_sync(FULLMASK, p1, l1);
        uint32_t sel = (g & 1) ? 0x7632u : 0x5410u;
        uint32_t bU0 = prmt_b32(s00, s01, sel);
        uint32_t bU1 = prmt_b32(s10, s11, sel);

        // ---- Phase B: U^T += X^T @ A (8 independent chains) ----
#pragma unroll
        for (int md = 0; md < 8; md++) {
            int ar = (sub >> 1) * 8 + rwl;
            int ac = 2 * md + (sub & 1);
            uint32_t addr = sb + (uint32_t)(ar * 16 + (ac ^ (ar & 7))) * 16u;
            uint32_t a0, a1, a2, a3;
            ldsm_x4_t(a0, a1, a2, a3, addr);
            mma16816(U[md], a0, a1, a2, a3, bU0, bU1);
        }
        __syncwarp();      // all reads done before this stage is overwritten
    }

    // ---- block-level reduction in shared ----
#pragma unroll
    for (int md = 0; md < 8; md++) {
        int d0 = md * 16 + g;
        atomicAdd(&sUsh[(2 * t) * D + d0],         U[md][0]);
        atomicAdd(&sUsh[(2 * t + 1) * D + d0],     U[md][1]);
        atomicAdd(&sUsh[(2 * t) * D + d0 + 8],     U[md][2]);
        atomicAdd(&sUsh[(2 * t + 1) * D + d0 + 8], U[md][3]);
    }
    dc0 += __shfl_xor_sync(FULLMASK, dc0, 4);
    dc0 += __shfl_xor_sync(FULLMASK, dc0, 8);
    dc0 += __shfl_xor_sync(FULLMASK, dc0, 16);
    dc1 += __shfl_xor_sync(FULLMASK, dc1, 4);
    dc1 += __shfl_xor_sync(FULLMASK, dc1, 8);
    dc1 += __shfl_xor_sync(FULLMASK, dc1, 16);
    if (l < 4) {
        atomicAdd(&sden[2 * t], dc0);
        atomicAdd(&sden[2 * t + 1], dc1);
    }
    __syncthreads();

    // ---- plain coalesced store to this block's private partial slot ----
    size_t part = (size_t)(b * ABLK + cx);
    float* gU = g_Upart + part * (NQ * D);
    for (int i = tid; i < NQ * D; i += 128) gU[i] = sUsh[i];
    if (tid < NQ) g_denpart[part * NQ + tid] = sden[tid];
}

// ============================================================
// Kernel 4 (per iter, 1024 thr): reduce partials ; updates ;
// GRU ; slots+FF.  thread = (e = tid>>3, q = tid&7).
// do_pre != 0: fused next-iteration qk/tt.
// ============================================================
__global__ void __launch_bounds__(1024) post_kernel(
        const float* __restrict__ wv, const float* __restrict__ bv,
        const float* __restrict__ gwi, const float* __restrict__ gwh,
        const float* __restrict__ gbi, const float* __restrict__ gbh,
        const float* __restrict__ w1, const float* __restrict__ b1,
        const float* __restrict__ w2, const float* __restrict__ b2,
        const float* __restrict__ lnw, const float* __restrict__ lnb,
        const float* __restrict__ wq, const float* __restrict__ bq,
        const float* __restrict__ wk, const float* __restrict__ bk,
        const float* __restrict__ lnqw, const float* __restrict__ lnqb,
        float* __restrict__ out, int write_out, int do_pre) {
    int row = blockIdx.x;
    int tid = threadIdx.x;
    int e = tid >> 3, q = tid & 7;
    int bb = row >> 3, ii = row & 7;                // batch, query
    __shared__ float sU[D], sUpd[D], sS[D], sM[H], red[32], sdp[ABLK];
    // ---- reduce den partials ----
    if (tid < ABLK) sdp[tid] = g_denpart[(bb * ABLK + tid) * NQ + ii];
    __syncthreads();
    float den = 0.f;
#pragma unroll 8
    for (int j = 0; j < ABLK; j++) den += sdp[j];   // broadcast reads
    // ---- reduce U partials: thread (e,q) sums ABLK/8 chunks ----
    float up = 0.f;
#pragma unroll
    for (int j = 0; j < ABLK / 8; j++)
        up += g_Upart[((size_t)(bb * ABLK + q * (ABLK / 8) + j) * NQ + ii) * D + e];
    up = octSum(up);
    float slot = g_slots[row * D + e];              // x8 redundant
    if (q == 0) {
        sU[e] = up / den;
        sS[e] = slot;
    }
    __syncthreads();
    float upd = octSum(qdot16(sU, wv + e * D, q));
    if (q == 0) sUpd[e] = upd + bv[e];
    __syncthreads();
    float gi[3], gh[3];
#pragma unroll
    for (int k = 0; k < 3; k++) {
        int gg = e + k * D;
        float ai = octSum(qdot16(sUpd, gwi + gg * D, q));
        float ah = octSum(qdot16(sS, gwh + gg * D, q));
        gi[k] = ai + gbi[gg];
        gh[k] = ah + gbh[gg];
    }
    float r = 1.0f / (1.0f + __expf(-(gi[0] + gh[0])));
    float z = 1.0f / (1.0f + __expf(-(gi[1] + gh[1])));
    float n = tanhf(gi[2] + r * gh[2]);
    float snew = (1.0f - z) * n + z * slot;         // same in all 8 roles
    float mean = blockSum1024(snew, red) * (1.0f / (8 * D));
    float d0 = snew - mean;
    float var = blockSum1024(d0 * d0, red) * (1.0f / (8 * D));
    float rstd = rsqrtf(var + LN_EPS);
    if (q == 0) sU[e] = d0 * rstd * lnw[e] + lnb[e];   // reuse sU as hidden
    __syncthreads();
    // MLP layer 1: output hh = tid>>1, half part = tid&1 (64 elems each)
    {
        int hh = tid >> 1, part = tid & 1;
        float a0 = 0.f, a1 = 0.f, a2 = 0.f, a3 = 0.f;
        const float4* m = (const float4*)(w1 + hh * D + part * 64);
        const float4* s4 = (const float4*)(sU + part * 64);
#pragma unroll
        for (int j = 0; j < 16; j++) {
            float4 mv = m[j];
            float4 sv = s4[j];
            a0 = fmaf(sv.x, mv.x, a0);
            a1 = fmaf(sv.y, mv.y, a1);
            a2 = fmaf(sv.z, mv.z, a2);
            a3 = fmaf(sv.w, mv.w, a3);
        }
        float v = (a0 + a1) + (a2 + a3);
        v += __shfl_xor_sync(FULLMASK, v, 1);
        if (part == 0) sM[hh] = fmaxf(v + b1[hh], 0.f);
    }
    __syncthreads();
    // MLP layer 2: output e, eighth q over H=512 (64 elems each)
    float onew;
    {
        float a0 = 0.f, a1 = 0.f, a2 = 0.f, a3 = 0.f;
        const float4* m = (const float4*)(w2 + e * H + q * 64);
        const float4* s4 = (const float4*)(sM + q * 64);
#pragma unroll
        for (int j = 0; j < 16; j++) {
            float4 mv = m[j];
            float4 sv = s4[j];
            a0 = fmaf(sv.x, mv.x, a0);
            a1 = fmaf(sv.y, mv.y, a1);
            a2 = fmaf(sv.z, mv.z, a2);
            a3 = fmaf(sv.w, mv.w, a3);
        }
        onew = octSum((a0 + a1) + (a2 + a3)) + b2[e] + snew;   // all lanes
        if (q == 0) {
            g_slots[row * D + e] = onew;
            if (write_out) out[row * D + e] = onew;
        }
    }
    if (!do_pre) return;

    // ---- fused pre for the NEXT iteration (onew in registers) ----
    __syncthreads();
    float mean2 = blockSum1024(onew, red) * (1.0f / (8 * D));
    float dd = onew - mean2;
    float var2 = blockSum1024(dd * dd, red) * (1.0f / (8 * D));
    float rstd2 = rsqrtf(var2 + LN_EPS);
    if (q == 0) sS[e] = dd * rstd2 * lnqw[e] + lnqb[e];   // reuse sS as h
    __syncthreads();
    float accq = octSum(qdot16(sS, wq + e * D, q));
    if (q == 0) sUpd[e] = accq + bq[e];                   // reuse sUpd as qvec
    __syncthreads();
    float qk = 0.f;
#pragma unroll 8
    for (int j = 0; j < 16; j++) {
        int d = q * 16 + j;
        qk = fmaf(sUpd[d], wk[d * D + e], qk);
    }
    qk = octSum(qk);
    if (q == 0) g_qk[row * D + e] = qk * SCALE;
    float tv = (q == 0) ? sUpd[e] * bk[e] : 0.f;
    float tb = blockSum1024(tv, red);
    if (tid == 0) g_tt[row] = tb * SCALE;
}

// ============================================================
extern "C" void kernel_launch(void* const* d_in, const int* in_sizes, int n_in,
                              void* d_out, int out_size) {
    (void)in_sizes; (void)n_in; (void)out_size;
    const float* queries = (const float*)d_in[0];
    const float* inputs  = (const float*)d_in[1];
    const float* wq  = (const float*)d_in[2];
    const float* bq  = (const float*)d_in[3];
    const float* wk  = (const float*)d_in[4];
    const float* bk  = (const float*)d_in[5];
    const float* wv  = (const float*)d_in[6];
    const float* bv  = (const float*)d_in[7];
    const float* gwi = (const float*)d_in[8];
    const float* gwh = (const float*)d_in[9];
    const float* gbi = (const float*)d_in[10];
    const float* gbh = (const float*)d_in[11];
    const float* w1  = (const float*)d_in[12];
    const float* b1  = (const float*)d_in[13];
    const float* w2  = (const float*)d_in[14];
    const float* b2  = (const float*)d_in[15];
    const float* ln_in_w = (const float*)d_in[16];
    const float* ln_in_b = (const float*)d_in[17];
    const float* ln_q_w  = (const float*)d_in[18];
    const float* ln_q_b  = (const float*)d_in[19];
    const float* ln_ff_w = (const float*)d_in[20];
    const float* ln_ff_b = (const float*)d_in[21];
    float* out = (float*)d_out;

    ln_in_kernel<<<B * NS / 8, 256>>>(inputs, ln_in_w, ln_in_b);
    pre_kernel<<<B * NQ, 512>>>(queries, wq, bq, wk, bk, ln_q_w, ln_q_b);
    for (int it = 0; it < ITERS; it++) {
        attn_kernel<<<dim3(ABLK, B), 128>>>();
        post_kernel<<<B * NQ, 1024>>>(wv, bv, gwi, gwh, gbi, gbh,
                                      w1, b1, w2, b2, ln_ff_w, ln_ff_b,
                                      wq, bq, wk, bk, ln_q_w, ln_q_b,
                                      out, it == ITERS - 1 ? 1 : 0,
                                      it < ITERS - 1 ? 1 : 0);
    }
}